// round 2
// baseline (speedup 1.0000x reference)
#include <cuda_runtime.h>

#define NN   50000
#define EE   800000
#define CH   128
#define NB   256      // graphs in batch
#define NCLS 10
#define MLPH 64
#define EPSV 1e-5f

// ---------------- scratch (static device globals; no allocation) ----------------
__device__ float g_deg[NN];          // degree, then dinv in place
__device__ float g_norm[EE];         // per-edge norm coefficient
__device__ float g_hlin[NN * CH];    // GEMM output (pre-aggregation)
__device__ float g_agg[NN * CH];     // aggregation accumulator
__device__ float g_hbuf[NN * CH];    // relu'd layer output (next layer input)
__device__ float g_chsum[CH];        // BN: sum h
__device__ float g_chsq[CH];         // BN: sum h^2
__device__ float g_gsum[NB * CH];    // per-graph pooled sums
__device__ float g_gcnt[NB];         // per-graph node counts

// ---------------- init ----------------
__global__ void init_kernel() {
    int i = blockIdx.x * blockDim.x + threadIdx.x;
    if (i < NN) g_deg[i] = 1.0f;                // self-loop weight
    if (i < CH) { g_chsum[i] = 0.f; g_chsq[i] = 0.f; }
    if (i < NB * CH) g_gsum[i] = 0.f;
    if (i < NB) g_gcnt[i] = 0.f;
}

// ---------------- degree / norm precompute ----------------
__global__ void deg_kernel(const int* __restrict__ dst, const float* __restrict__ ew) {
    int e = blockIdx.x * blockDim.x + threadIdx.x;
    if (e < EE) atomicAdd(&g_deg[dst[e]], ew[e]);
}

__global__ void dinv_kernel() {
    int n = blockIdx.x * blockDim.x + threadIdx.x;
    if (n < NN) g_deg[n] = rsqrtf(g_deg[n]);    // deg >= 1 always
}

__global__ void norm_kernel(const int* __restrict__ src, const int* __restrict__ dst,
                            const float* __restrict__ ew) {
    int e = blockIdx.x * blockDim.x + threadIdx.x;
    if (e < EE) g_norm[e] = g_deg[src[e]] * ew[e] * g_deg[dst[e]];
}

// ---------------- SGEMM: hlin = A @ W ; agg = hlin * dinv^2 ----------------
// Tile: 64 rows x 128 cols (full H), BK=16. 256 threads: warp ty=tid/32 owns 8
// rows, lane tx=tid%32 owns 4 cols. A staged transposed in smem (broadcast
// reads), W tile read as float4 (conflict-free).
__global__ void gemm_kernel(const float* __restrict__ A, const float* __restrict__ W) {
    __shared__ float As[16][65];   // [kk][row], pad 65 to soften store conflicts
    __shared__ float Bs[16][128];

    int tid = threadIdx.x;
    int tx = tid & 31;
    int ty = tid >> 5;
    int row0 = blockIdx.x * 64;

    float acc[8][4];
#pragma unroll
    for (int i = 0; i < 8; i++)
#pragma unroll
        for (int j = 0; j < 4; j++) acc[i][j] = 0.f;

    int lr = tid >> 2;            // 0..63 : row for A load
    int lk = (tid & 3) * 4;       // 0,4,8,12 : k offset for A load

    for (int k0 = 0; k0 < CH; k0 += 16) {
        int gr = row0 + lr;
        float4 av = make_float4(0.f, 0.f, 0.f, 0.f);
        if (gr < NN) av = *(const float4*)&A[gr * CH + k0 + lk];
        As[lk + 0][lr] = av.x; As[lk + 1][lr] = av.y;
        As[lk + 2][lr] = av.z; As[lk + 3][lr] = av.w;
#pragma unroll
        for (int i = 0; i < 2; i++) {
            int v = tid + i * 256;
            int wr = v >> 5;
            int wc = (v & 31) * 4;
            *(float4*)&Bs[wr][wc] = *(const float4*)&W[(k0 + wr) * CH + wc];
        }
        __syncthreads();
#pragma unroll
        for (int kk = 0; kk < 16; kk++) {
            float4 b4 = *(const float4*)&Bs[kk][tx * 4];
#pragma unroll
            for (int i = 0; i < 8; i++) {
                float a = As[kk][ty * 8 + i];
                acc[i][0] += a * b4.x;
                acc[i][1] += a * b4.y;
                acc[i][2] += a * b4.z;
                acc[i][3] += a * b4.w;
            }
        }
        __syncthreads();
    }

#pragma unroll
    for (int i = 0; i < 8; i++) {
        int n = row0 + ty * 8 + i;
        if (n < NN) {
            float di = g_deg[n];           // dinv
            float d2 = di * di;
            int idx = n * CH + tx * 4;
            float4 h = make_float4(acc[i][0], acc[i][1], acc[i][2], acc[i][3]);
            *(float4*)&g_hlin[idx] = h;
            float4 ag = make_float4(h.x * d2, h.y * d2, h.z * d2, h.w * d2);
            *(float4*)&g_agg[idx] = ag;
        }
    }
}

// ---------------- edge aggregation: agg[dst] += norm * hlin[src] ----------------
// One warp per edge; lane handles 4 channels (float4). Gather is L2-resident.
__global__ void edge_kernel(const int* __restrict__ src, const int* __restrict__ dst) {
    int gid = blockIdx.x * blockDim.x + threadIdx.x;
    int e = gid >> 5;
    if (e >= EE) return;
    int lane = gid & 31;
    int s = __ldg(&src[e]);
    int d = __ldg(&dst[e]);
    float nm = g_norm[e];
    float4 v = *(const float4*)&g_hlin[s * CH + lane * 4];
    float* p = &g_agg[d * CH + lane * 4];
    asm volatile("red.global.add.v4.f32 [%0], {%1, %2, %3, %4};"
                 :: "l"(p), "f"(v.x * nm), "f"(v.y * nm), "f"(v.z * nm), "f"(v.w * nm)
                 : "memory");
}

// ---------------- post: hbuf = relu(agg + b) ----------------
__global__ void post_kernel(const float* __restrict__ bias) {
    int i = blockIdx.x * blockDim.x + threadIdx.x;   // float4 index
    if (i >= NN * CH / 4) return;
    float4 a = *(const float4*)&g_agg[i * 4];
    int c = (i * 4) & (CH - 1);
    float4 b = *(const float4*)&bias[c];
    float4 r;
    r.x = fmaxf(a.x + b.x, 0.f);
    r.y = fmaxf(a.y + b.y, 0.f);
    r.z = fmaxf(a.z + b.z, 0.f);
    r.w = fmaxf(a.w + b.w, 0.f);
    *(float4*)&g_hbuf[i * 4] = r;
}

// ---------------- per-graph node counts ----------------
__global__ void count_kernel(const int* __restrict__ batch) {
    int n = blockIdx.x * blockDim.x + threadIdx.x;
    if (n < NN) atomicAdd(&g_gcnt[batch[n]], 1.0f);
}

// ---------------- BN stats + pooled sums ----------------
// batch is sorted -> run-length local accumulation, atomic flush on boundaries.
#define NPB 256
__global__ void pool_kernel(const int* __restrict__ batch) {
    int c = threadIdx.x;                 // 128 threads = channels
    int n0 = blockIdx.x * NPB;
    int nend = min(n0 + NPB, NN);
    if (n0 >= NN) return;
    float s = 0.f, sq = 0.f, loc = 0.f;
    int curg = __ldg(&batch[n0]);
    for (int n = n0; n < nend; n++) {
        float v = g_hbuf[n * CH + c];
        s += v; sq += v * v;
        int g = __ldg(&batch[n]);
        if (g != curg) {
            atomicAdd(&g_gsum[curg * CH + c], loc);
            loc = 0.f;
            curg = g;
        }
        loc += v;
    }
    atomicAdd(&g_gsum[curg * CH + c], loc);
    atomicAdd(&g_chsum[c], s);
    atomicAdd(&g_chsq[c], sq);
}

// ---------------- head: BN affine on pooled means + 2-layer MLP ----------------
__global__ void head_kernel(const float* __restrict__ gamma, const float* __restrict__ beta,
                            const float* __restrict__ Wm1, const float* __restrict__ bm1,
                            const float* __restrict__ Wm2, const float* __restrict__ bm2,
                            float* __restrict__ out) {
    __shared__ float gs[CH];
    __shared__ float tt[MLPH];
    int b = blockIdx.x;
    int c = threadIdx.x;
    float mu = g_chsum[c] * (1.0f / NN);
    float var = g_chsq[c] * (1.0f / NN) - mu * mu;
    float rs = rsqrtf(var + EPSV);
    float cnt = fmaxf(g_gcnt[b], 1.0f);
    gs[c] = (g_gsum[b * CH + c] / cnt - mu) * rs * gamma[c] + beta[c];
    __syncthreads();
    if (c < MLPH) {
        float acc = bm1[c];
#pragma unroll 8
        for (int k = 0; k < CH; k++) acc += gs[k] * Wm1[k * MLPH + c];
        tt[c] = acc;
    }
    __syncthreads();
    if (c < NCLS) {
        float acc = bm2[c];
#pragma unroll 8
        for (int k = 0; k < MLPH; k++) acc += tt[k] * Wm2[k * NCLS + c];
        out[b * NCLS + c] = acc;
    }
}

// ---------------- launch ----------------
extern "C" void kernel_launch(void* const* d_in, const int* in_sizes, int n_in,
                              void* d_out, int out_size) {
    const float* x     = (const float*)d_in[0];
    const int*   ei    = (const int*)  d_in[1];   // [2, E]
    const float* ea    = (const float*)d_in[2];
    const int*   batch = (const int*)  d_in[3];
    const float* W1    = (const float*)d_in[4];
    const float* b1    = (const float*)d_in[5];
    const float* W2    = (const float*)d_in[6];
    const float* b2    = (const float*)d_in[7];
    const float* W3    = (const float*)d_in[8];
    const float* b3    = (const float*)d_in[9];
    const float* gamma = (const float*)d_in[10];
    const float* beta  = (const float*)d_in[11];
    const float* Wm1   = (const float*)d_in[12];
    const float* bm1   = (const float*)d_in[13];
    const float* Wm2   = (const float*)d_in[14];
    const float* bm2   = (const float*)d_in[15];
    float* out = (float*)d_out;

    const int* src = ei;
    const int* dst = ei + EE;

    void* hbuf_ptr = nullptr;
    cudaGetSymbolAddress(&hbuf_ptr, g_hbuf);

    init_kernel<<<(NN + 255) / 256, 256>>>();
    deg_kernel<<<(EE + 255) / 256, 256>>>(dst, ea);
    dinv_kernel<<<(NN + 255) / 256, 256>>>();
    norm_kernel<<<(EE + 255) / 256, 256>>>(src, dst, ea);
    count_kernel<<<(NN + 255) / 256, 256>>>(batch);

    const float* Ws[3] = {W1, W2, W3};
    const float* bs[3] = {b1, b2, b3};
    const float* inp = x;
    for (int l = 0; l < 3; l++) {
        gemm_kernel<<<(NN + 63) / 64, 256>>>(inp, Ws[l]);
        edge_kernel<<<(int)(((long long)EE * 32 + 255) / 256), 256>>>(src, dst);
        post_kernel<<<(NN * CH / 4 + 255) / 256, 256>>>(bs[l]);
        inp = (const float*)hbuf_ptr;
    }

    pool_kernel<<<(NN + NPB - 1) / NPB, CH>>>(batch);
    head_kernel<<<NB, CH>>>(gamma, beta, Wm1, bm1, Wm2, bm2, out);
}

// round 5
// speedup vs baseline: 1.1985x; 1.1985x over previous
#include <cuda_runtime.h>

#define NN   50000
#define EE   800000
#define CH   128
#define NB   256
#define NCLS 10
#define MLPH 64
#define EPSV 1e-5f

// ---------------- scratch ----------------
__device__ float g_deg[NN];            // degree, then dinv in place
__device__ int   g_degcnt[NN];         // integer in-degree
__device__ int   g_rowptr[NN + 1];     // CSR row pointers (by dst)
__device__ int   g_woff[NN];           // write cursors for fill
__device__ int   g_csr_src[EE];        // CSR: src node per slot
__device__ float g_csr_norm[EE];       // CSR: edge norm per slot
__device__ float g_hlin[NN * CH];      // GEMM output
__device__ float g_hbuf[NN * CH];      // layer output (relu'd)
__device__ float g_chsum[CH];
__device__ float g_chsq[CH];
__device__ float g_gsum[NB * CH];
__device__ float g_gcnt[NB];

// ---------------- init ----------------
__global__ void init_kernel() {
    int i = blockIdx.x * blockDim.x + threadIdx.x;
    if (i < NN) { g_deg[i] = 1.0f; g_degcnt[i] = 0; }
    if (i < CH) { g_chsum[i] = 0.f; g_chsq[i] = 0.f; }
    if (i < NB * CH) g_gsum[i] = 0.f;
    if (i < NB) g_gcnt[i] = 0.f;
}

// ---------------- degree (weighted float + int count) ----------------
__global__ void deg_kernel(const int* __restrict__ dst, const float* __restrict__ ew) {
    int e = blockIdx.x * blockDim.x + threadIdx.x;
    if (e < EE) {
        int d = dst[e];
        atomicAdd(&g_deg[d], ew[e]);
        atomicAdd(&g_degcnt[d], 1);
    }
}

__global__ void dinv_kernel() {
    int n = blockIdx.x * blockDim.x + threadIdx.x;
    if (n < NN) g_deg[n] = rsqrtf(g_deg[n]);
}

// ---------------- single-block scan over g_degcnt -> rowptr/woff ----------------
__global__ void scan_kernel() {
    __shared__ int sums[1024];
    int t = threadIdx.x;
    const int per = (NN + 1023) / 1024;          // 49
    int beg = t * per;
    int end = min(beg + per, NN);
    int s = 0;
    for (int i = beg; i < end; i++) s += g_degcnt[i];
    sums[t] = s;
    __syncthreads();
    for (int off = 1; off < 1024; off <<= 1) {
        int v = 0;
        if (t >= off) v = sums[t - off];
        __syncthreads();
        if (t >= off) sums[t] += v;
        __syncthreads();
    }
    int run = (t > 0) ? sums[t - 1] : 0;         // exclusive prefix
    for (int i = beg; i < end; i++) {
        int c = g_degcnt[i];
        g_rowptr[i] = run;
        g_woff[i] = run;
        run += c;
    }
    if (t == 1023) g_rowptr[NN] = EE;
}

// ---------------- CSR fill (also computes norm) ----------------
__global__ void fill_kernel(const int* __restrict__ src, const int* __restrict__ dst,
                            const float* __restrict__ ew) {
    int e = blockIdx.x * blockDim.x + threadIdx.x;
    if (e >= EE) return;
    int s = src[e];
    int d = dst[e];
    float nm = g_deg[s] * ew[e] * g_deg[d];
    int pos = atomicAdd(&g_woff[d], 1);
    g_csr_src[pos] = s;
    g_csr_norm[pos] = nm;
}

// ---------------- per-graph node counts ----------------
__global__ void count_kernel(const int* __restrict__ batch) {
    int n = blockIdx.x * blockDim.x + threadIdx.x;
    if (n < NN) atomicAdd(&g_gcnt[batch[n]], 1.0f);
}

// ---------------- SGEMM: hlin = A @ W  (128x128 tile, BK=16, 8x8 micro) ----------------
__global__ void gemm_kernel(const float* __restrict__ A, const float* __restrict__ W) {
    __shared__ float As[16][132];    // [k][row], 132*4=528B rows (16B aligned)
    __shared__ float Bs[16][128];

    int tid = threadIdx.x;
    int tx = tid & 15;               // 0..15 -> cols tx*8
    int ty = tid >> 4;               // 0..15 -> rows ty*8
    int row0 = blockIdx.x * 128;

    float acc[8][8];
#pragma unroll
    for (int i = 0; i < 8; i++)
#pragma unroll
        for (int j = 0; j < 8; j++) acc[i][j] = 0.f;

    for (int k0 = 0; k0 < CH; k0 += 16) {
        // load A: 512 float4 (128 rows x 16 k), 2 per thread
#pragma unroll
        for (int l = 0; l < 2; l++) {
            int f = tid + l * 256;
            int r = f >> 2;                   // 0..127
            int kq = (f & 3) * 4;             // 0,4,8,12
            int gr = row0 + r;
            float4 av = make_float4(0.f, 0.f, 0.f, 0.f);
            if (gr < NN) av = *(const float4*)&A[gr * CH + k0 + kq];
            As[kq + 0][r] = av.x; As[kq + 1][r] = av.y;
            As[kq + 2][r] = av.z; As[kq + 3][r] = av.w;
        }
        // load W: 512 float4 (16 k x 128 cols), 2 per thread
#pragma unroll
        for (int l = 0; l < 2; l++) {
            int f = tid + l * 256;
            int kr = f >> 5;                  // 0..15
            int kc = (f & 31) * 4;
            *(float4*)&Bs[kr][kc] = *(const float4*)&W[(k0 + kr) * CH + kc];
        }
        __syncthreads();
#pragma unroll
        for (int kk = 0; kk < 16; kk++) {
            float4 a0 = *(const float4*)&As[kk][ty * 8];
            float4 a1 = *(const float4*)&As[kk][ty * 8 + 4];
            float4 b0 = *(const float4*)&Bs[kk][tx * 8];
            float4 b1 = *(const float4*)&Bs[kk][tx * 8 + 4];
            float ar[8] = {a0.x, a0.y, a0.z, a0.w, a1.x, a1.y, a1.z, a1.w};
            float br[8] = {b0.x, b0.y, b0.z, b0.w, b1.x, b1.y, b1.z, b1.w};
#pragma unroll
            for (int i = 0; i < 8; i++)
#pragma unroll
                for (int j = 0; j < 8; j++) acc[i][j] += ar[i] * br[j];
        }
        __syncthreads();
    }

#pragma unroll
    for (int i = 0; i < 8; i++) {
        int n = row0 + ty * 8 + i;
        if (n < NN) {
            *(float4*)&g_hlin[n * CH + tx * 8]     = make_float4(acc[i][0], acc[i][1], acc[i][2], acc[i][3]);
            *(float4*)&g_hlin[n * CH + tx * 8 + 4] = make_float4(acc[i][4], acc[i][5], acc[i][6], acc[i][7]);
        }
    }
}

// ---------------- aggregation: warp per dst node, fused bias+relu ----------------
// acc = hlin[n]*dinv^2 + sum_e norm_e * hlin[src_e]; hbuf = relu(acc + bias)
__global__ void agg_kernel(const float* __restrict__ bias) {
    int gid = blockIdx.x * blockDim.x + threadIdx.x;
    int n = gid >> 5;
    if (n >= NN) return;
    int lane = gid & 31;

    float di = g_deg[n];
    float d2 = di * di;
    float4 self = *(const float4*)&g_hlin[n * CH + lane * 4];
    float4 acc = make_float4(self.x * d2, self.y * d2, self.z * d2, self.w * d2);

    int beg = g_rowptr[n];
    int end = g_rowptr[n + 1];
#pragma unroll 2
    for (int p = beg; p < end; p++) {
        int s = __ldg(&g_csr_src[p]);
        float nm = __ldg(&g_csr_norm[p]);
        float4 v = *(const float4*)&g_hlin[s * CH + lane * 4];
        acc.x += nm * v.x;
        acc.y += nm * v.y;
        acc.z += nm * v.z;
        acc.w += nm * v.w;
    }

    float4 b = *(const float4*)&bias[lane * 4];
    float4 r;
    r.x = fmaxf(acc.x + b.x, 0.f);
    r.y = fmaxf(acc.y + b.y, 0.f);
    r.z = fmaxf(acc.z + b.z, 0.f);
    r.w = fmaxf(acc.w + b.w, 0.f);
    *(float4*)&g_hbuf[n * CH + lane * 4] = r;
}

// ---------------- BN stats + pooled sums ----------------
#define NPB 256
__global__ void pool_kernel(const int* __restrict__ batch) {
    int c = threadIdx.x;
    int n0 = blockIdx.x * NPB;
    int nend = min(n0 + NPB, NN);
    if (n0 >= NN) return;
    float s = 0.f, sq = 0.f, loc = 0.f;
    int curg = __ldg(&batch[n0]);
    for (int n = n0; n < nend; n++) {
        float v = g_hbuf[n * CH + c];
        s += v; sq += v * v;
        int g = __ldg(&batch[n]);
        if (g != curg) {
            atomicAdd(&g_gsum[curg * CH + c], loc);
            loc = 0.f;
            curg = g;
        }
        loc += v;
    }
    atomicAdd(&g_gsum[curg * CH + c], loc);
    atomicAdd(&g_chsum[c], s);
    atomicAdd(&g_chsq[c], sq);
}

// ---------------- head ----------------
__global__ void head_kernel(const float* __restrict__ gamma, const float* __restrict__ beta,
                            const float* __restrict__ Wm1, const float* __restrict__ bm1,
                            const float* __restrict__ Wm2, const float* __restrict__ bm2,
                            float* __restrict__ out) {
    __shared__ float gs[CH];
    __shared__ float tt[MLPH];
    int b = blockIdx.x;
    int c = threadIdx.x;
    float mu = g_chsum[c] * (1.0f / NN);
    float var = g_chsq[c] * (1.0f / NN) - mu * mu;
    float rs = rsqrtf(var + EPSV);
    float cnt = fmaxf(g_gcnt[b], 1.0f);
    gs[c] = (g_gsum[b * CH + c] / cnt - mu) * rs * gamma[c] + beta[c];
    __syncthreads();
    if (c < MLPH) {
        float acc = bm1[c];
#pragma unroll 8
        for (int k = 0; k < CH; k++) acc += gs[k] * Wm1[k * MLPH + c];
        tt[c] = acc;
    }
    __syncthreads();
    if (c < NCLS) {
        float acc = bm2[c];
#pragma unroll 8
        for (int k = 0; k < MLPH; k++) acc += tt[k] * Wm2[k * NCLS + c];
        out[b * NCLS + c] = acc;
    }
}

// ---------------- launch ----------------
extern "C" void kernel_launch(void* const* d_in, const int* in_sizes, int n_in,
                              void* d_out, int out_size) {
    const float* x     = (const float*)d_in[0];
    const int*   ei    = (const int*)  d_in[1];
    const float* ea    = (const float*)d_in[2];
    const int*   batch = (const int*)  d_in[3];
    const float* W1    = (const float*)d_in[4];
    const float* b1    = (const float*)d_in[5];
    const float* W2    = (const float*)d_in[6];
    const float* b2    = (const float*)d_in[7];
    const float* W3    = (const float*)d_in[8];
    const float* b3    = (const float*)d_in[9];
    const float* gamma = (const float*)d_in[10];
    const float* beta  = (const float*)d_in[11];
    const float* Wm1   = (const float*)d_in[12];
    const float* bm1   = (const float*)d_in[13];
    const float* Wm2   = (const float*)d_in[14];
    const float* bm2   = (const float*)d_in[15];
    float* out = (float*)d_out;

    const int* src = ei;
    const int* dst = ei + EE;

    void* hbuf_ptr = nullptr;
    cudaGetSymbolAddress(&hbuf_ptr, g_hbuf);

    init_kernel<<<(NN + 255) / 256, 256>>>();
    deg_kernel<<<(EE + 255) / 256, 256>>>(dst, ea);
    dinv_kernel<<<(NN + 255) / 256, 256>>>();
    scan_kernel<<<1, 1024>>>();
    fill_kernel<<<(EE + 255) / 256, 256>>>(src, dst, ea);
    count_kernel<<<(NN + 255) / 256, 256>>>(batch);

    const float* Ws[3] = {W1, W2, W3};
    const float* bs[3] = {b1, b2, b3};
    const float* inp = x;
    for (int l = 0; l < 3; l++) {
        gemm_kernel<<<(NN + 127) / 128, 256>>>(inp, Ws[l]);
        agg_kernel<<<(int)(((long long)NN * 32 + 255) / 256), 256>>>(bs[l]);
        inp = (const float*)hbuf_ptr;
    }

    pool_kernel<<<(NN + NPB - 1) / NPB, CH>>>(batch);
    head_kernel<<<NB, CH>>>(gamma, beta, Wm1, bm1, Wm2, bm2, out);
}

// round 7
// speedup vs baseline: 1.4369x; 1.1989x over previous
#include <cuda_runtime.h>

#define NN   50000
#define EE   800000
#define CH   128
#define NB   256
#define NCLS 10
#define MLPH 64
#define EPSV 1e-5f

#define SCAN_BLK 512
#define NBLK ((NN + SCAN_BLK - 1) / SCAN_BLK)   // 98

// ---------------- scratch ----------------
__device__ float g_deg[NN];            // degree, then dinv in place
__device__ int   g_degcnt[NN];         // integer in-degree
__device__ int   g_rowptr[NN + 1];     // CSR row pointers (by dst)
__device__ int   g_woff[NN];           // write cursors for fill
__device__ int   g_bsum[NBLK];         // per-block degcnt sums
__device__ int   g_boff[NBLK];         // exclusive prefix of block sums
__device__ int   g_csr_src[EE];        // CSR: src node per slot
__device__ float g_csr_norm[EE];       // CSR: edge norm per slot
__device__ float g_hlin[NN * CH];      // GEMM output
__device__ float g_hbuf[NN * CH];      // layer output (relu'd)
__device__ float g_chsum[CH];
__device__ float g_chsq[CH];
__device__ float g_gsum[NB * CH];
__device__ float g_gcnt[NB];

// ---------------- init ----------------
__global__ void init_kernel() {
    int i = blockIdx.x * blockDim.x + threadIdx.x;
    if (i < NN) { g_deg[i] = 1.0f; g_degcnt[i] = 0; }
    if (i < CH) { g_chsum[i] = 0.f; g_chsq[i] = 0.f; }
    if (i < NB * CH) g_gsum[i] = 0.f;
    if (i < NB) g_gcnt[i] = 0.f;
}

// ---------------- degree (weighted float + int count) ----------------
__global__ void deg_kernel(const int* __restrict__ dst, const float* __restrict__ ew) {
    int e = blockIdx.x * blockDim.x + threadIdx.x;
    if (e < EE) {
        int d = dst[e];
        atomicAdd(&g_deg[d], ew[e]);
        atomicAdd(&g_degcnt[d], 1);
    }
}

__global__ void dinv_kernel() {
    int n = blockIdx.x * blockDim.x + threadIdx.x;
    if (n < NN) g_deg[n] = rsqrtf(g_deg[n]);
}

// ---------------- hierarchical scan: stage 1 — per-block sums ----------------
__global__ void blocksum_kernel() {
    __shared__ int ws[SCAN_BLK / 32];
    int t = threadIdx.x;
    int i = blockIdx.x * SCAN_BLK + t;
    int v = (i < NN) ? g_degcnt[i] : 0;
#pragma unroll
    for (int o = 16; o > 0; o >>= 1) v += __shfl_down_sync(0xffffffffu, v, o);
    if ((t & 31) == 0) ws[t >> 5] = v;
    __syncthreads();
    if (t < 32) {
        int s = (t < SCAN_BLK / 32) ? ws[t] : 0;
#pragma unroll
        for (int o = 16; o > 0; o >>= 1) s += __shfl_down_sync(0xffffffffu, s, o);
        if (t == 0) g_bsum[blockIdx.x] = s;
    }
}

// ---------------- stage 2 — scan the 98 block sums (1 block) ----------------
__global__ void bscan_kernel() {
    __shared__ int sh[128];
    int t = threadIdx.x;
    sh[t] = (t < NBLK) ? g_bsum[t] : 0;
    __syncthreads();
#pragma unroll
    for (int o = 1; o < 128; o <<= 1) {
        int v = (t >= o) ? sh[t - o] : 0;
        __syncthreads();
        sh[t] += v;
        __syncthreads();
    }
    if (t < NBLK) g_boff[t] = sh[t] - g_bsum[t];   // exclusive
}

// ---------------- stage 3 — per-element exclusive scan + offset ----------------
__global__ void rowptr_kernel() {
    __shared__ int ws[SCAN_BLK / 32];
    int t = threadIdx.x;
    int i = blockIdx.x * SCAN_BLK + t;
    int v = (i < NN) ? g_degcnt[i] : 0;
    int lane = t & 31;
    int wid = t >> 5;
    // warp inclusive scan
    int sc = v;
#pragma unroll
    for (int o = 1; o < 32; o <<= 1) {
        int u = __shfl_up_sync(0xffffffffu, sc, o);
        if (lane >= o) sc += u;
    }
    if (lane == 31) ws[wid] = sc;
    __syncthreads();
    if (t < 32) {
        int s = (t < SCAN_BLK / 32) ? ws[t] : 0;
#pragma unroll
        for (int o = 1; o < 32; o <<= 1) {
            int u = __shfl_up_sync(0xffffffffu, s, o);
            if ((t & 31) >= o) s += u;
        }
        if (t < SCAN_BLK / 32) ws[t] = s;
    }
    __syncthreads();
    int excl = sc - v + ((wid > 0) ? ws[wid - 1] : 0) + g_boff[blockIdx.x];
    if (i < NN) { g_rowptr[i] = excl; g_woff[i] = excl; }
    if (i == NN - 1) g_rowptr[NN] = EE;
}

// ---------------- CSR fill (also computes norm) ----------------
__global__ void fill_kernel(const int* __restrict__ src, const int* __restrict__ dst,
                            const float* __restrict__ ew) {
    int e = blockIdx.x * blockDim.x + threadIdx.x;
    if (e >= EE) return;
    int s = src[e];
    int d = dst[e];
    float nm = g_deg[s] * ew[e] * g_deg[d];
    int pos = atomicAdd(&g_woff[d], 1);
    g_csr_src[pos] = s;
    g_csr_norm[pos] = nm;
}

// ---------------- per-graph node counts ----------------
__global__ void count_kernel(const int* __restrict__ batch) {
    int n = blockIdx.x * blockDim.x + threadIdx.x;
    if (n < NN) atomicAdd(&g_gcnt[batch[n]], 1.0f);
}

// ---------------- SGEMM: hlin = A @ W  (128x128 tile, BK=16, 8x8 micro) ----------------
__global__ void gemm_kernel(const float* __restrict__ A, const float* __restrict__ W) {
    __shared__ float As[16][132];
    __shared__ float Bs[16][128];

    int tid = threadIdx.x;
    int tx = tid & 15;
    int ty = tid >> 4;
    int row0 = blockIdx.x * 128;

    float acc[8][8];
#pragma unroll
    for (int i = 0; i < 8; i++)
#pragma unroll
        for (int j = 0; j < 8; j++) acc[i][j] = 0.f;

    for (int k0 = 0; k0 < CH; k0 += 16) {
#pragma unroll
        for (int l = 0; l < 2; l++) {
            int f = tid + l * 256;
            int r = f >> 2;
            int kq = (f & 3) * 4;
            int gr = row0 + r;
            float4 av = make_float4(0.f, 0.f, 0.f, 0.f);
            if (gr < NN) av = *(const float4*)&A[gr * CH + k0 + kq];
            As[kq + 0][r] = av.x; As[kq + 1][r] = av.y;
            As[kq + 2][r] = av.z; As[kq + 3][r] = av.w;
        }
#pragma unroll
        for (int l = 0; l < 2; l++) {
            int f = tid + l * 256;
            int kr = f >> 5;
            int kc = (f & 31) * 4;
            *(float4*)&Bs[kr][kc] = *(const float4*)&W[(k0 + kr) * CH + kc];
        }
        __syncthreads();
#pragma unroll
        for (int kk = 0; kk < 16; kk++) {
            float4 a0 = *(const float4*)&As[kk][ty * 8];
            float4 a1 = *(const float4*)&As[kk][ty * 8 + 4];
            float4 b0 = *(const float4*)&Bs[kk][tx * 8];
            float4 b1 = *(const float4*)&Bs[kk][tx * 8 + 4];
            float ar[8] = {a0.x, a0.y, a0.z, a0.w, a1.x, a1.y, a1.z, a1.w};
            float br[8] = {b0.x, b0.y, b0.z, b0.w, b1.x, b1.y, b1.z, b1.w};
#pragma unroll
            for (int i = 0; i < 8; i++)
#pragma unroll
                for (int j = 0; j < 8; j++) acc[i][j] += ar[i] * br[j];
        }
        __syncthreads();
    }

#pragma unroll
    for (int i = 0; i < 8; i++) {
        int n = row0 + ty * 8 + i;
        if (n < NN) {
            *(float4*)&g_hlin[n * CH + tx * 8]     = make_float4(acc[i][0], acc[i][1], acc[i][2], acc[i][3]);
            *(float4*)&g_hlin[n * CH + tx * 8 + 4] = make_float4(acc[i][4], acc[i][5], acc[i][6], acc[i][7]);
        }
    }
}

// ---------------- aggregation: warp per dst node, fused bias+relu ----------------
__global__ void agg_kernel(const float* __restrict__ bias) {
    int gid = blockIdx.x * blockDim.x + threadIdx.x;
    int n = gid >> 5;
    if (n >= NN) return;
    int lane = gid & 31;

    float di = g_deg[n];
    float d2 = di * di;
    float4 self = *(const float4*)&g_hlin[n * CH + lane * 4];
    float4 acc = make_float4(self.x * d2, self.y * d2, self.z * d2, self.w * d2);

    int beg = g_rowptr[n];
    int end = g_rowptr[n + 1];
#pragma unroll 2
    for (int p = beg; p < end; p++) {
        int s = __ldg(&g_csr_src[p]);
        float nm = __ldg(&g_csr_norm[p]);
        float4 v = *(const float4*)&g_hlin[s * CH + lane * 4];
        acc.x += nm * v.x;
        acc.y += nm * v.y;
        acc.z += nm * v.z;
        acc.w += nm * v.w;
    }

    float4 b = *(const float4*)&bias[lane * 4];
    float4 r;
    r.x = fmaxf(acc.x + b.x, 0.f);
    r.y = fmaxf(acc.y + b.y, 0.f);
    r.z = fmaxf(acc.z + b.z, 0.f);
    r.w = fmaxf(acc.w + b.w, 0.f);
    *(float4*)&g_hbuf[n * CH + lane * 4] = r;
}

// ---------------- BN stats + pooled sums ----------------
#define NPB 256
__global__ void pool_kernel(const int* __restrict__ batch) {
    int c = threadIdx.x;
    int n0 = blockIdx.x * NPB;
    int nend = min(n0 + NPB, NN);
    if (n0 >= NN) return;
    float s = 0.f, sq = 0.f, loc = 0.f;
    int curg = __ldg(&batch[n0]);
    for (int n = n0; n < nend; n++) {
        float v = g_hbuf[n * CH + c];
        s += v; sq += v * v;
        int g = __ldg(&batch[n]);
        if (g != curg) {
            atomicAdd(&g_gsum[curg * CH + c], loc);
            loc = 0.f;
            curg = g;
        }
        loc += v;
    }
    atomicAdd(&g_gsum[curg * CH + c], loc);
    atomicAdd(&g_chsum[c], s);
    atomicAdd(&g_chsq[c], sq);
}

// ---------------- head ----------------
__global__ void head_kernel(const float* __restrict__ gamma, const float* __restrict__ beta,
                            const float* __restrict__ Wm1, const float* __restrict__ bm1,
                            const float* __restrict__ Wm2, const float* __restrict__ bm2,
                            float* __restrict__ out) {
    __shared__ float gs[CH];
    __shared__ float tt[MLPH];
    int b = blockIdx.x;
    int c = threadIdx.x;
    float mu = g_chsum[c] * (1.0f / NN);
    float var = g_chsq[c] * (1.0f / NN) - mu * mu;
    float rs = rsqrtf(var + EPSV);
    float cnt = fmaxf(g_gcnt[b], 1.0f);
    gs[c] = (g_gsum[b * CH + c] / cnt - mu) * rs * gamma[c] + beta[c];
    __syncthreads();
    if (c < MLPH) {
        float acc = bm1[c];
#pragma unroll 8
        for (int k = 0; k < CH; k++) acc += gs[k] * Wm1[k * MLPH + c];
        tt[c] = acc;
    }
    __syncthreads();
    if (c < NCLS) {
        float acc = bm2[c];
#pragma unroll 8
        for (int k = 0; k < MLPH; k++) acc += tt[k] * Wm2[k * NCLS + c];
        out[b * NCLS + c] = acc;
    }
}

// ---------------- launch ----------------
extern "C" void kernel_launch(void* const* d_in, const int* in_sizes, int n_in,
                              void* d_out, int out_size) {
    const float* x     = (const float*)d_in[0];
    const int*   ei    = (const int*)  d_in[1];
    const float* ea    = (const float*)d_in[2];
    const int*   batch = (const int*)  d_in[3];
    const float* W1    = (const float*)d_in[4];
    const float* b1    = (const float*)d_in[5];
    const float* W2    = (const float*)d_in[6];
    const float* b2    = (const float*)d_in[7];
    const float* W3    = (const float*)d_in[8];
    const float* b3    = (const float*)d_in[9];
    const float* gamma = (const float*)d_in[10];
    const float* beta  = (const float*)d_in[11];
    const float* Wm1   = (const float*)d_in[12];
    const float* bm1   = (const float*)d_in[13];
    const float* Wm2   = (const float*)d_in[14];
    const float* bm2   = (const float*)d_in[15];
    float* out = (float*)d_out;

    const int* src = ei;
    const int* dst = ei + EE;

    void* hbuf_ptr = nullptr;
    cudaGetSymbolAddress(&hbuf_ptr, g_hbuf);

    init_kernel<<<(NN + 255) / 256, 256>>>();
    deg_kernel<<<(EE + 255) / 256, 256>>>(dst, ea);
    dinv_kernel<<<(NN + 255) / 256, 256>>>();
    blocksum_kernel<<<NBLK, SCAN_BLK>>>();
    bscan_kernel<<<1, 128>>>();
    rowptr_kernel<<<NBLK, SCAN_BLK>>>();
    fill_kernel<<<(EE + 255) / 256, 256>>>(src, dst, ea);
    count_kernel<<<(NN + 255) / 256, 256>>>(batch);

    const float* Ws[3] = {W1, W2, W3};
    const float* bs[3] = {b1, b2, b3};
    const float* inp = x;
    for (int l = 0; l < 3; l++) {
        gemm_kernel<<<(NN + 127) / 128, 256>>>(inp, Ws[l]);
        agg_kernel<<<(int)(((long long)NN * 32 + 255) / 256), 256>>>(bs[l]);
        inp = (const float*)hbuf_ptr;
    }

    pool_kernel<<<(NN + NPB - 1) / NPB, CH>>>(batch);
    head_kernel<<<NB, CH>>>(gamma, beta, Wm1, bm1, Wm2, bm2, out);
}

// round 13
// speedup vs baseline: 1.6224x; 1.1291x over previous
#include <cuda_runtime.h>
#include <cuda_bf16.h>

#define NN   50000
#define EE   800000
#define CH   128
#define NB   256
#define NCLS 10
#define MLPH 64
#define EPSV 1e-5f

#define SCAN_BLK 512
#define NBLK ((NN + SCAN_BLK - 1) / SCAN_BLK)   // 98

// padded row length for bf16 tiles: 136 elements (272B) -> conflict-free ldmatrix
#define LDK 136
#define WIMG_U32 (CH * LDK / 2)    // 8704 unsigned per image

// ---------------- scratch ----------------
__device__ float g_deg[NN];
__device__ int   g_degcnt[NN];
__device__ int   g_rowptr[NN + 1];
__device__ int   g_woff[NN];
__device__ int   g_bsum[NBLK];
__device__ int   g_boff[NBLK];
__device__ int   g_csr_src[EE];
__device__ float g_csr_norm[EE];
__device__ float g_hlin[NN * CH];
__device__ float g_hbuf[NN * CH];
__device__ float g_chsum[CH];
__device__ float g_chsq[CH];
__device__ float g_gsum[NB * CH];
__device__ float g_gcnt[NB];
// W split-bf16 images, padded [n][LDK] layout (n = output col, k contiguous)
__device__ unsigned g_Wimg_hi[3][WIMG_U32];
__device__ unsigned g_Wimg_lo[3][WIMG_U32];

// ---------------- mma helpers (arch-agnostic PTX, compiles at compute_103) ----------------
__device__ __forceinline__ unsigned smem_u32(const void* p) {
    unsigned a;
    asm("{ .reg .u64 t; cvta.to.shared.u64 t, %1; cvt.u32.u64 %0, t; }" : "=r"(a) : "l"(p));
    return a;
}
__device__ __forceinline__ void ldsm_x4(unsigned* r, unsigned addr) {
    asm volatile("ldmatrix.sync.aligned.m8n8.x4.shared.b16 {%0,%1,%2,%3}, [%4];"
                 : "=r"(r[0]), "=r"(r[1]), "=r"(r[2]), "=r"(r[3]) : "r"(addr));
}
__device__ __forceinline__ void mma16816(float* c, const unsigned* a, unsigned b0, unsigned b1) {
    asm volatile(
        "mma.sync.aligned.m16n8k16.row.col.f32.bf16.bf16.f32 "
        "{%0,%1,%2,%3}, {%4,%5,%6,%7}, {%8,%9}, {%0,%1,%2,%3};"
        : "+f"(c[0]), "+f"(c[1]), "+f"(c[2]), "+f"(c[3])
        : "r"(a[0]), "r"(a[1]), "r"(a[2]), "r"(a[3]), "r"(b0), "r"(b1));
}
__device__ __forceinline__ unsigned pack_bf16_hi(float a0, float a1,
                                                 unsigned* lo) {
    __nv_bfloat16 h0 = __float2bfloat16(a0);
    __nv_bfloat16 h1 = __float2bfloat16(a1);
    __nv_bfloat16 l0 = __float2bfloat16(a0 - __bfloat162float(h0));
    __nv_bfloat16 l1 = __float2bfloat16(a1 - __bfloat162float(h1));
    *lo = (unsigned)__bfloat16_as_ushort(l0) | ((unsigned)__bfloat16_as_ushort(l1) << 16);
    return (unsigned)__bfloat16_as_ushort(h0) | ((unsigned)__bfloat16_as_ushort(h1) << 16);
}

// SMEM map (dynamic): A_hi, A_lo, W_hi, W_lo, each 128*LDK*2 = 34816 B
#define TILE_B (CH * LDK * 2)
#define SM_AHI 0
#define SM_ALO TILE_B
#define SM_WHI (2 * TILE_B)
#define SM_WLO (3 * TILE_B)
#define SM_TOTAL (4 * TILE_B)

// ---------------- W split precompute (B[n][k] = W[k][n], padded rows) ----------------
__global__ void wconv_kernel(const float* __restrict__ W, int layer) {
    int g = blockIdx.x * blockDim.x + threadIdx.x;   // 8192 pairs
    if (g >= CH * CH / 2) return;
    int n = g >> 6;               // 0..127
    int kp = (g & 63) * 2;        // even k
    float a0 = W[kp * CH + n];
    float a1 = W[(kp + 1) * CH + n];
    unsigned lo;
    unsigned hi = pack_bf16_hi(a0, a1, &lo);
    int idx = (n * LDK + kp) / 2;
    g_Wimg_hi[layer][idx] = hi;
    g_Wimg_lo[layer][idx] = lo;
}

// ---------------- HMMA GEMM: one 128x128 tile per CTA, split-bf16 3 products ----------------
__global__ void __launch_bounds__(256, 1) gemm_mma_kernel(const float* __restrict__ A, int layer) {
    extern __shared__ char smem[];
    unsigned sb = smem_u32(smem);
    int tid = threadIdx.x;
    int wid = tid >> 5;
    int lane = tid & 31;
    int row0 = blockIdx.x * 128;

    // copy W images (global, L2-resident) into SMEM
    {
        const uint4* wh = (const uint4*)g_Wimg_hi[layer];
        const uint4* wl = (const uint4*)g_Wimg_lo[layer];
        for (int i = tid; i < TILE_B / 16; i += 256) {
            *(uint4*)(smem + SM_WHI + i * 16) = wh[i];
            *(uint4*)(smem + SM_WLO + i * 16) = wl[i];
        }
    }
    // convert A tile: thread handles one half-row (64 k) of one row
    {
        int r = tid >> 1;
        int k0 = (tid & 1) * 64;
        int row = row0 + r;
        unsigned* dh = (unsigned*)(smem + SM_AHI) + (r * LDK + k0) / 2;
        unsigned* dl = (unsigned*)(smem + SM_ALO) + (r * LDK + k0) / 2;
        if (row < NN) {
            const float* ap = &A[row * CH + k0];
#pragma unroll
            for (int i = 0; i < 16; i++) {
                float4 v = *(const float4*)&ap[i * 4];
                unsigned lo0, lo1;
                unsigned hi0 = pack_bf16_hi(v.x, v.y, &lo0);
                unsigned hi1 = pack_bf16_hi(v.z, v.w, &lo1);
                dh[i * 2] = hi0; dh[i * 2 + 1] = hi1;
                dl[i * 2] = lo0; dl[i * 2 + 1] = lo1;
            }
        } else {
#pragma unroll
            for (int i = 0; i < 32; i++) { dh[i] = 0u; dl[i] = 0u; }
        }
    }
    __syncthreads();

    // warp tile: 32 rows x 64 cols. 8 warps = 4 (m) x 2 (n)
    int wm0 = (wid >> 1) * 32;
    int wn0 = (wid & 1) * 64;

    float c[2][8][4];
#pragma unroll
    for (int mt = 0; mt < 2; mt++)
#pragma unroll
        for (int nt = 0; nt < 8; nt++)
#pragma unroll
            for (int j = 0; j < 4; j++) c[mt][nt][j] = 0.f;

    int rsel = lane & 15;
    int ksel = (lane >> 4) * 8;

#pragma unroll
    for (int ch = 0; ch < 8; ch++) {
        int k0 = ch * 16;
        unsigned ahi[2][4], alo[2][4];
#pragma unroll
        for (int mt = 0; mt < 2; mt++) {
            unsigned aaddr = sb + SM_AHI + ((wm0 + mt * 16 + rsel) * LDK + k0 + ksel) * 2;
            ldsm_x4(ahi[mt], aaddr);
            ldsm_x4(alo[mt], aaddr + (SM_ALO - SM_AHI));
        }
#pragma unroll
        for (int nb = 0; nb < 4; nb++) {
            unsigned baddr = sb + SM_WHI + ((wn0 + nb * 16 + rsel) * LDK + k0 + ksel) * 2;
            unsigned bh[4], bl[4];
            ldsm_x4(bh, baddr);
            ldsm_x4(bl, baddr + (SM_WLO - SM_WHI));
#pragma unroll
            for (int mt = 0; mt < 2; mt++) {
                // n-tile low (cols nb*16 .. +7): b frag {r0, r2}
                mma16816(c[mt][nb * 2],     ahi[mt], bh[0], bh[2]);
                mma16816(c[mt][nb * 2],     alo[mt], bh[0], bh[2]);
                mma16816(c[mt][nb * 2],     ahi[mt], bl[0], bl[2]);
                // n-tile high (cols +8 .. +15): b frag {r1, r3}
                mma16816(c[mt][nb * 2 + 1], ahi[mt], bh[1], bh[3]);
                mma16816(c[mt][nb * 2 + 1], alo[mt], bh[1], bh[3]);
                mma16816(c[mt][nb * 2 + 1], ahi[mt], bl[1], bl[3]);
            }
        }
    }

    // epilogue: c0,c1 -> (row, col..col+1); c2,c3 -> (row+8, ...)
    int lrow = lane >> 2;
    int lcol = (lane & 3) * 2;
#pragma unroll
    for (int mt = 0; mt < 2; mt++) {
        int r1 = row0 + wm0 + mt * 16 + lrow;
        int r2 = r1 + 8;
#pragma unroll
        for (int nt = 0; nt < 8; nt++) {
            int col = wn0 + nt * 8 + lcol;
            if (r1 < NN) *(float2*)&g_hlin[r1 * CH + col] = make_float2(c[mt][nt][0], c[mt][nt][1]);
            if (r2 < NN) *(float2*)&g_hlin[r2 * CH + col] = make_float2(c[mt][nt][2], c[mt][nt][3]);
        }
    }
}

// ---------------- init ----------------
__global__ void init_kernel() {
    int i = blockIdx.x * blockDim.x + threadIdx.x;
    if (i < NN) { g_deg[i] = 1.0f; g_degcnt[i] = 0; }
    if (i < CH) { g_chsum[i] = 0.f; g_chsq[i] = 0.f; }
    if (i < NB * CH) g_gsum[i] = 0.f;
    if (i < NB) g_gcnt[i] = 0.f;
}

__global__ void deg_kernel(const int* __restrict__ dst, const float* __restrict__ ew) {
    int e = blockIdx.x * blockDim.x + threadIdx.x;
    if (e < EE) {
        int d = dst[e];
        atomicAdd(&g_deg[d], ew[e]);
        atomicAdd(&g_degcnt[d], 1);
    }
}

__global__ void dinv_kernel() {
    int n = blockIdx.x * blockDim.x + threadIdx.x;
    if (n < NN) g_deg[n] = rsqrtf(g_deg[n]);
}

__global__ void blocksum_kernel() {
    __shared__ int ws[SCAN_BLK / 32];
    int t = threadIdx.x;
    int i = blockIdx.x * SCAN_BLK + t;
    int v = (i < NN) ? g_degcnt[i] : 0;
#pragma unroll
    for (int o = 16; o > 0; o >>= 1) v += __shfl_down_sync(0xffffffffu, v, o);
    if ((t & 31) == 0) ws[t >> 5] = v;
    __syncthreads();
    if (t < 32) {
        int s = (t < SCAN_BLK / 32) ? ws[t] : 0;
#pragma unroll
        for (int o = 16; o > 0; o >>= 1) s += __shfl_down_sync(0xffffffffu, s, o);
        if (t == 0) g_bsum[blockIdx.x] = s;
    }
}

__global__ void bscan_kernel() {
    __shared__ int sh[128];
    int t = threadIdx.x;
    sh[t] = (t < NBLK) ? g_bsum[t] : 0;
    __syncthreads();
#pragma unroll
    for (int o = 1; o < 128; o <<= 1) {
        int v = (t >= o) ? sh[t - o] : 0;
        __syncthreads();
        sh[t] += v;
        __syncthreads();
    }
    if (t < NBLK) g_boff[t] = sh[t] - g_bsum[t];
}

__global__ void rowptr_kernel() {
    __shared__ int ws[SCAN_BLK / 32];
    int t = threadIdx.x;
    int i = blockIdx.x * SCAN_BLK + t;
    int v = (i < NN) ? g_degcnt[i] : 0;
    int lane = t & 31;
    int wid = t >> 5;
    int sc = v;
#pragma unroll
    for (int o = 1; o < 32; o <<= 1) {
        int u = __shfl_up_sync(0xffffffffu, sc, o);
        if (lane >= o) sc += u;
    }
    if (lane == 31) ws[wid] = sc;
    __syncthreads();
    if (t < 32) {
        int s = (t < SCAN_BLK / 32) ? ws[t] : 0;
#pragma unroll
        for (int o = 1; o < 32; o <<= 1) {
            int u = __shfl_up_sync(0xffffffffu, s, o);
            if ((t & 31) >= o) s += u;
        }
        if (t < SCAN_BLK / 32) ws[t] = s;
    }
    __syncthreads();
    int excl = sc - v + ((wid > 0) ? ws[wid - 1] : 0) + g_boff[blockIdx.x];
    if (i < NN) { g_rowptr[i] = excl; g_woff[i] = excl; }
    if (i == NN - 1) g_rowptr[NN] = EE;
}

__global__ void fill_kernel(const int* __restrict__ src, const int* __restrict__ dst,
                            const float* __restrict__ ew) {
    int e = blockIdx.x * blockDim.x + threadIdx.x;
    if (e >= EE) return;
    int s = src[e];
    int d = dst[e];
    float nm = g_deg[s] * ew[e] * g_deg[d];
    int pos = atomicAdd(&g_woff[d], 1);
    g_csr_src[pos] = s;
    g_csr_norm[pos] = nm;
}

__global__ void count_kernel(const int* __restrict__ batch) {
    int n = blockIdx.x * blockDim.x + threadIdx.x;
    if (n < NN) atomicAdd(&g_gcnt[batch[n]], 1.0f);
}

// ---------------- aggregation: warp per dst node, fused bias+relu ----------------
__global__ void agg_kernel(const float* __restrict__ bias) {
    int gid = blockIdx.x * blockDim.x + threadIdx.x;
    int n = gid >> 5;
    if (n >= NN) return;
    int lane = gid & 31;

    float di = g_deg[n];
    float d2 = di * di;
    float4 self = *(const float4*)&g_hlin[n * CH + lane * 4];
    float4 acc = make_float4(self.x * d2, self.y * d2, self.z * d2, self.w * d2);

    int beg = g_rowptr[n];
    int end = g_rowptr[n + 1];
#pragma unroll 2
    for (int p = beg; p < end; p++) {
        int s = __ldg(&g_csr_src[p]);
        float nm = __ldg(&g_csr_norm[p]);
        float4 v = *(const float4*)&g_hlin[s * CH + lane * 4];
        acc.x += nm * v.x;
        acc.y += nm * v.y;
        acc.z += nm * v.z;
        acc.w += nm * v.w;
    }

    float4 b = *(const float4*)&bias[lane * 4];
    float4 r;
    r.x = fmaxf(acc.x + b.x, 0.f);
    r.y = fmaxf(acc.y + b.y, 0.f);
    r.z = fmaxf(acc.z + b.z, 0.f);
    r.w = fmaxf(acc.w + b.w, 0.f);
    *(float4*)&g_hbuf[n * CH + lane * 4] = r;
}

// ---------------- BN stats + pooled sums ----------------
#define NPB 256
__global__ void pool_kernel(const int* __restrict__ batch) {
    int c = threadIdx.x;
    int n0 = blockIdx.x * NPB;
    int nend = min(n0 + NPB, NN);
    if (n0 >= NN) return;
    float s = 0.f, sq = 0.f, loc = 0.f;
    int curg = __ldg(&batch[n0]);
    for (int n = n0; n < nend; n++) {
        float v = g_hbuf[n * CH + c];
        s += v; sq += v * v;
        int g = __ldg(&batch[n]);
        if (g != curg) {
            atomicAdd(&g_gsum[curg * CH + c], loc);
            loc = 0.f;
            curg = g;
        }
        loc += v;
    }
    atomicAdd(&g_gsum[curg * CH + c], loc);
    atomicAdd(&g_chsum[c], s);
    atomicAdd(&g_chsq[c], sq);
}

// ---------------- head ----------------
__global__ void head_kernel(const float* __restrict__ gamma, const float* __restrict__ beta,
                            const float* __restrict__ Wm1, const float* __restrict__ bm1,
                            const float* __restrict__ Wm2, const float* __restrict__ bm2,
                            float* __restrict__ out) {
    __shared__ float gs[CH];
    __shared__ float tt[MLPH];
    int b = blockIdx.x;
    int c = threadIdx.x;
    float mu = g_chsum[c] * (1.0f / NN);
    float var = g_chsq[c] * (1.0f / NN) - mu * mu;
    float rs = rsqrtf(var + EPSV);
    float cnt = fmaxf(g_gcnt[b], 1.0f);
    gs[c] = (g_gsum[b * CH + c] / cnt - mu) * rs * gamma[c] + beta[c];
    __syncthreads();
    if (c < MLPH) {
        float acc = bm1[c];
#pragma unroll 8
        for (int k = 0; k < CH; k++) acc += gs[k] * Wm1[k * MLPH + c];
        tt[c] = acc;
    }
    __syncthreads();
    if (c < NCLS) {
        float acc = bm2[c];
#pragma unroll 8
        for (int k = 0; k < MLPH; k++) acc += tt[k] * Wm2[k * NCLS + c];
        out[b * NCLS + c] = acc;
    }
}

// ---------------- launch ----------------
extern "C" void kernel_launch(void* const* d_in, const int* in_sizes, int n_in,
                              void* d_out, int out_size) {
    const float* x     = (const float*)d_in[0];
    const int*   ei    = (const int*)  d_in[1];
    const float* ea    = (const float*)d_in[2];
    const int*   batch = (const int*)  d_in[3];
    const float* W1    = (const float*)d_in[4];
    const float* b1    = (const float*)d_in[5];
    const float* W2    = (const float*)d_in[6];
    const float* b2    = (const float*)d_in[7];
    const float* W3    = (const float*)d_in[8];
    const float* b3    = (const float*)d_in[9];
    const float* gamma = (const float*)d_in[10];
    const float* beta  = (const float*)d_in[11];
    const float* Wm1   = (const float*)d_in[12];
    const float* bm1   = (const float*)d_in[13];
    const float* Wm2   = (const float*)d_in[14];
    const float* bm2   = (const float*)d_in[15];
    float* out = (float*)d_out;

    const int* src = ei;
    const int* dst = ei + EE;

    cudaFuncSetAttribute(gemm_mma_kernel, cudaFuncAttributeMaxDynamicSharedMemorySize, SM_TOTAL);

    void* hbuf_ptr = nullptr;
    cudaGetSymbolAddress(&hbuf_ptr, g_hbuf);

    init_kernel<<<(NN + 255) / 256, 256>>>();
    deg_kernel<<<(EE + 255) / 256, 256>>>(dst, ea);
    wconv_kernel<<<(CH * CH / 2 + 255) / 256, 256>>>(W1, 0);
    wconv_kernel<<<(CH * CH / 2 + 255) / 256, 256>>>(W2, 1);
    wconv_kernel<<<(CH * CH / 2 + 255) / 256, 256>>>(W3, 2);
    dinv_kernel<<<(NN + 255) / 256, 256>>>();
    blocksum_kernel<<<NBLK, SCAN_BLK>>>();
    bscan_kernel<<<1, 128>>>();
    rowptr_kernel<<<NBLK, SCAN_BLK>>>();
    fill_kernel<<<(EE + 255) / 256, 256>>>(src, dst, ea);
    count_kernel<<<(NN + 255) / 256, 256>>>(batch);

    const float* bs[3] = {b1, b2, b3};
    const float* inp = x;
    for (int l = 0; l < 3; l++) {
        gemm_mma_kernel<<<(NN + 127) / 128, 256, SM_TOTAL>>>(inp, l);
        agg_kernel<<<(int)(((long long)NN * 32 + 255) / 256), 256>>>(bs[l]);
        inp = (const float*)hbuf_ptr;
    }

    pool_kernel<<<(NN + NPB - 1) / NPB, CH>>>(batch);
    head_kernel<<<NB, CH>>>(gamma, beta, Wm1, bm1, Wm2, bm2, out);
}